// round 3
// baseline (speedup 1.0000x reference)
#include <cuda_runtime.h>
#include <cstdint>

#define NN 50000
#define NE 800000

// ---------------- scratch (device globals; no runtime allocation) ----------------
__device__ int   g_is64;
__device__ int   g_src[NE];
__device__ int   g_dst[NE];
__device__ float g_coef[NE];

__device__ float g_deg[NN];
__device__ float g_dinv[NN];
__device__ float g_dinv2[NN];

__device__ float g_h1[NN * 32];     // id 0
__device__ float g_agg1[NN * 32];   // id 1
__device__ float g_z1[NN * 32];     // id 2
__device__ float g_agg2[NN * 32];   // id 3
__device__ float g_h2[NN * 64];     // id 4
__device__ float g_z2[NN * 64];     // id 5
__device__ float g_agg3[NN * 64];   // id 6
__device__ float g_h3[NN * 128];    // id 7
__device__ float g_z3[NN * 128];    // id 8
__device__ float g_m1[NN * 256];    // id 9
__device__ float g_m2[NN * 128];    // id 10
__device__ float g_m3[NN * 64];     // id 11

__device__ float g_sum1[32],  g_sq1[32];
__device__ float g_sum2[64],  g_sq2[64];
__device__ float g_sum3[128], g_sq3[128];
__device__ float g_scale1[32],  g_shift1[32];
__device__ float g_scale2[64],  g_shift2[64];
__device__ float g_scale3[128], g_shift3[128];

__device__ __forceinline__ float* dev_buf(int id) {
    switch (id) {
        case 0:  return g_h1;
        case 1:  return g_agg1;
        case 2:  return g_z1;
        case 3:  return g_agg2;
        case 4:  return g_h2;
        case 5:  return g_z2;
        case 6:  return g_agg3;
        case 7:  return g_h3;
        case 8:  return g_z3;
        case 9:  return g_m1;
        case 10: return g_m2;
        default: return g_m3;
    }
}

// ---------------- edge-index dtype detect + convert ----------------
__global__ void k_detect(const int* __restrict__ w) {
    if (threadIdx.x == 0 && blockIdx.x == 0) {
        int is64 = 1;
        for (int i = 0; i < 128; i++) {
            int lo = w[2 * i], hi = w[2 * i + 1];
            if (hi != 0 || lo < 0 || lo >= NN) { is64 = 0; break; }
        }
        g_is64 = is64;
    }
}

__global__ void k_convert(const int* __restrict__ w) {
    int e = blockIdx.x * blockDim.x + threadIdx.x;
    if (e >= NE) return;
    int s, d;
    if (g_is64) { s = w[2 * e]; d = w[2 * (NE + e)]; }
    else        { s = w[e];     d = w[NE + e]; }
    // clamp defensively (avoids wild atomics even if detection were ever wrong)
    s = min(max(s, 0), NN - 1);
    d = min(max(d, 0), NN - 1);
    g_src[e] = s;
    g_dst[e] = d;
}

// ---------------- setup ----------------
__global__ void k_init() {
    int i = blockIdx.x * blockDim.x + threadIdx.x;
    if (i < NN) g_deg[i] = 1.0f;
    if (i < 128) { g_sum3[i] = 0.f; g_sq3[i] = 0.f; }
    if (i < 64)  { g_sum2[i] = 0.f; g_sq2[i] = 0.f; }
    if (i < 32)  { g_sum1[i] = 0.f; g_sq1[i] = 0.f; }
}

__global__ void k_deg() {
    int e = blockIdx.x * blockDim.x + threadIdx.x;
    if (e < NE) atomicAdd(&g_deg[g_dst[e]], 1.0f);
}

__global__ void k_dinv() {
    int i = blockIdx.x * blockDim.x + threadIdx.x;
    if (i < NN) {
        float r = rsqrtf(g_deg[i]);
        g_dinv[i]  = r;
        g_dinv2[i] = r * r;
    }
}

__global__ void k_coef() {
    int e = blockIdx.x * blockDim.x + threadIdx.x;
    if (e < NE) g_coef[e] = g_dinv[g_src[e]] * g_dinv[g_dst[e]];
}

// ---------------- GEMM: C[n,F] = A[n,K] @ W[K,F] ----------------
// EPI: 0 plain | 1 store C and C2 = C*dinv2[row] | 2 +bias,ReLU | 3 +bias
template <int BM, int BN, int BK, int TM, int TN, int EPI>
__launch_bounds__(256)
__global__ void k_gemm(const float* __restrict__ Aext, int aId,
                       const float* __restrict__ W,
                       const float* __restrict__ bias,
                       float* __restrict__ Cext, int cId, int c2Id,
                       int nrows, int K, int F) {
    const float* A = Aext ? Aext : dev_buf(aId);
    float* C = Cext ? Cext : dev_buf(cId);
    float* C2 = (EPI == 1) ? dev_buf(c2Id) : nullptr;

    constexpr int ASTR = BM + 4;
    __shared__ float As[BK * ASTR];              // transposed A tile [BK][BM]
    __shared__ float Ws[BK * BN];                // W tile [BK][BN]

    const int tid  = threadIdx.x;
    const int tx   = tid % (BN / TN);
    const int ty   = tid / (BN / TN);
    const int row0 = blockIdx.x * BM;
    const int c0   = blockIdx.y * BN;

    float acc[TM][TN];
#pragma unroll
    for (int i = 0; i < TM; i++)
#pragma unroll
        for (int j = 0; j < TN; j++) acc[i][j] = 0.f;

    for (int k0 = 0; k0 < K; k0 += BK) {
#pragma unroll
        for (int i = tid; i < BM * BK / 4; i += 256) {
            int r = i / (BK / 4);
            int c = (i % (BK / 4)) * 4;
            float4 v = make_float4(0.f, 0.f, 0.f, 0.f);
            if (row0 + r < nrows)
                v = *reinterpret_cast<const float4*>(&A[(size_t)(row0 + r) * K + k0 + c]);
            As[(c + 0) * ASTR + r] = v.x;
            As[(c + 1) * ASTR + r] = v.y;
            As[(c + 2) * ASTR + r] = v.z;
            As[(c + 3) * ASTR + r] = v.w;
        }
#pragma unroll
        for (int i = tid; i < BK * BN / 4; i += 256) {
            int kr = i / (BN / 4);
            int cc = (i % (BN / 4)) * 4;
            int gc = c0 + cc;
            float4 v;
            if (((F & 3) == 0) && (gc + 3 < F)) {
                v = *reinterpret_cast<const float4*>(&W[(size_t)(k0 + kr) * F + gc]);
            } else {
                v.x = (gc + 0 < F) ? W[(size_t)(k0 + kr) * F + gc + 0] : 0.f;
                v.y = (gc + 1 < F) ? W[(size_t)(k0 + kr) * F + gc + 1] : 0.f;
                v.z = (gc + 2 < F) ? W[(size_t)(k0 + kr) * F + gc + 2] : 0.f;
                v.w = (gc + 3 < F) ? W[(size_t)(k0 + kr) * F + gc + 3] : 0.f;
            }
            *reinterpret_cast<float4*>(&Ws[kr * BN + cc]) = v;
        }
        __syncthreads();

#pragma unroll
        for (int kk = 0; kk < BK; ++kk) {
            float a[TM], w[TN];
#pragma unroll
            for (int i = 0; i < TM; i++) a[i] = As[kk * ASTR + ty * TM + i];
#pragma unroll
            for (int j = 0; j < TN; j++) w[j] = Ws[kk * BN + tx * TN + j];
#pragma unroll
            for (int i = 0; i < TM; i++)
#pragma unroll
                for (int j = 0; j < TN; j++) acc[i][j] = fmaf(a[i], w[j], acc[i][j]);
        }
        __syncthreads();
    }

#pragma unroll
    for (int i = 0; i < TM; i++) {
        int row = row0 + ty * TM + i;
        if (row >= nrows) continue;
#pragma unroll
        for (int j = 0; j < TN; j++) {
            int col = c0 + tx * TN + j;
            if (col >= F) continue;
            float v = acc[i][j];
            if (EPI == 2 || EPI == 3) v += bias[col];
            if (EPI == 2) v = fmaxf(v, 0.f);
            C[(size_t)row * F + col] = v;
            if (EPI == 1) C2[(size_t)row * F + col] = v * g_dinv2[row];
        }
    }
}

// ---------------- edge scatter: agg[dst] += h[src] * coef[e] ----------------
template <int F>
__global__ void k_scatter(int hId, int aggId) {
    const float* __restrict__ h = dev_buf(hId);
    float* __restrict__ agg = dev_buf(aggId);
    const int L = F / 4;
    long long gid = (long long)blockIdx.x * blockDim.x + threadIdx.x;
    if (gid >= (long long)NE * L) return;
    int e = (int)(gid / L);
    int f = (int)(gid % L) * 4;
    int s = g_src[e];
    int d = g_dst[e];
    float c = g_coef[e];
    float4 v = *reinterpret_cast<const float4*>(&h[(size_t)s * F + f]);
    float* dst = &agg[(size_t)d * F + f];
    atomicAdd(dst + 0, v.x * c);
    atomicAdd(dst + 1, v.y * c);
    atomicAdd(dst + 2, v.z * c);
    atomicAdd(dst + 3, v.w * c);
}

// ---------------- BN statistics ----------------
template <int F, int LAYER>
__global__ void k_bnstats(int xId) {
    const float* __restrict__ X = dev_buf(xId);
    float* sum = (LAYER == 1) ? g_sum1 : (LAYER == 2) ? g_sum2 : g_sum3;
    float* sq  = (LAYER == 1) ? g_sq1  : (LAYER == 2) ? g_sq2  : g_sq3;
    constexpr int RP = 256 / F;
    __shared__ float sh[256], shq[256];
    int col = threadIdx.x % F;
    int rl  = threadIdx.x / F;
    float s = 0.f, q = 0.f;
    for (int r = blockIdx.x * RP + rl; r < NN; r += gridDim.x * RP) {
        float v = X[(size_t)r * F + col];
        s += v;
        q += v * v;
    }
    sh[threadIdx.x]  = s;
    shq[threadIdx.x] = q;
    __syncthreads();
    if (rl == 0) {
        for (int t = 1; t < RP; t++) { s += sh[t * F + col]; q += shq[t * F + col]; }
        atomicAdd(&sum[col], s);
        atomicAdd(&sq[col], q);
    }
}

template <int F, int LAYER>
__global__ void k_bnfinal(const float* __restrict__ g, const float* __restrict__ be) {
    const float* sum = (LAYER == 1) ? g_sum1 : (LAYER == 2) ? g_sum2 : g_sum3;
    const float* sq  = (LAYER == 1) ? g_sq1  : (LAYER == 2) ? g_sq2  : g_sq3;
    float* scale = (LAYER == 1) ? g_scale1 : (LAYER == 2) ? g_scale2 : g_scale3;
    float* shift = (LAYER == 1) ? g_shift1 : (LAYER == 2) ? g_shift2 : g_shift3;
    int i = threadIdx.x;
    if (i < F) {
        float mean = sum[i] * (1.0f / NN);
        float var  = sq[i] * (1.0f / NN) - mean * mean;
        float sc   = g[i] * rsqrtf(var + 1e-5f);
        scale[i] = sc;
        shift[i] = be[i] - mean * sc;
    }
}

// ---------------- BN apply + ReLU (+ optional self-loop init of next agg) ----------------
template <int F, int LAYER, bool SELF>
__global__ void k_map(int xId, int zId, int aggId) {
    const float* __restrict__ X = dev_buf(xId);
    float* __restrict__ Z = dev_buf(zId);
    const float* scale = (LAYER == 1) ? g_scale1 : (LAYER == 2) ? g_scale2 : g_scale3;
    const float* shift = (LAYER == 1) ? g_shift1 : (LAYER == 2) ? g_shift2 : g_shift3;
    int i = blockIdx.x * blockDim.x + threadIdx.x;
    if (i >= NN * F) return;
    int col = i & (F - 1);
    float z = fmaxf(fmaf(X[i], scale[col], shift[col]), 0.f);
    Z[i] = z;
    if (SELF) {
        float* __restrict__ AGG = dev_buf(aggId);
        AGG[i] = z * g_dinv2[i / F];
    }
}

// ---------------- launch ----------------
extern "C" void kernel_launch(void* const* d_in, const int* in_sizes, int n_in,
                              void* d_out, int out_size) {
    (void)in_sizes; (void)n_in; (void)out_size;
    const float* x   = (const float*)d_in[0];
    const int*   eiw = (const int*)d_in[1];      // int32 words (int64 handled by detect)
    const float* W1  = (const float*)d_in[2];
    const float* W2  = (const float*)d_in[4];
    const float* W3  = (const float*)d_in[6];
    const float* g1  = (const float*)d_in[8];  const float* be1 = (const float*)d_in[9];
    const float* g2  = (const float*)d_in[10]; const float* be2 = (const float*)d_in[11];
    const float* g3  = (const float*)d_in[12]; const float* be3 = (const float*)d_in[13];
    const float* Wf1 = (const float*)d_in[14]; const float* bf1 = (const float*)d_in[15];
    const float* Wf2 = (const float*)d_in[16]; const float* bf2 = (const float*)d_in[17];
    const float* Wf3 = (const float*)d_in[18]; const float* bf3 = (const float*)d_in[19];
    const float* Wf4 = (const float*)d_in[20]; const float* bf4 = (const float*)d_in[21];
    float* out = (float*)d_out;

    const int RB = (NN + 63) / 64;

    k_detect<<<1, 32>>>(eiw);
    k_convert<<<(NE + 255) / 256, 256>>>(eiw);
    k_init<<<(NN + 255) / 256, 256>>>();
    k_deg<<<(NE + 255) / 256, 256>>>();
    k_dinv<<<(NN + 255) / 256, 256>>>();
    k_coef<<<(NE + 255) / 256, 256>>>();

    // ids: 0 h1, 1 agg1, 2 z1, 3 agg2, 4 h2, 5 z2, 6 agg3, 7 h3, 8 z3, 9 m1, 10 m2, 11 m3

    // layer 1: h1 = x@W1 ; agg1 = self + scatter ; BN+ReLU -> z1 (+ self init agg2)
    k_gemm<64, 32, 32, 4, 2, 1><<<dim3(RB, 1), 256>>>(x, -1, W1, nullptr, nullptr, 0, 1, NN, 128, 32);
    k_scatter<32><<<(NE * 8 + 255) / 256, 256>>>(0, 1);
    k_bnstats<32, 1><<<232, 256>>>(1);
    k_bnfinal<32, 1><<<1, 32>>>(g1, be1);
    k_map<32, 1, true><<<(NN * 32 + 255) / 256, 256>>>(1, 2, 3);

    // layer 2: aggregate first (32 feats), then GEMM to 64
    k_scatter<32><<<(NE * 8 + 255) / 256, 256>>>(2, 3);
    k_gemm<64, 64, 32, 4, 4, 0><<<dim3(RB, 1), 256>>>(nullptr, 3, W2, nullptr, nullptr, 4, -1, NN, 32, 64);
    k_bnstats<64, 2><<<232, 256>>>(4);
    k_bnfinal<64, 2><<<1, 64>>>(g2, be2);
    k_map<64, 2, true><<<(NN * 64 + 255) / 256, 256>>>(4, 5, 6);

    // layer 3: aggregate first (64 feats), then GEMM to 128
    k_scatter<64><<<(NE * 16 + 255) / 256, 256>>>(5, 6);
    k_gemm<64, 64, 32, 4, 4, 0><<<dim3(RB, 2), 256>>>(nullptr, 6, W3, nullptr, nullptr, 7, -1, NN, 64, 128);
    k_bnstats<128, 3><<<232, 256>>>(7);
    k_bnfinal<128, 3><<<1, 128>>>(g3, be3);
    k_map<128, 3, false><<<(NN * 128 + 255) / 256, 256>>>(7, 8, -1);

    // MLP head
    k_gemm<64, 64, 32, 4, 4, 2><<<dim3(RB, 4), 256>>>(nullptr, 8, Wf1, bf1, nullptr, 9, -1, NN, 128, 256);
    k_gemm<64, 64, 32, 4, 4, 2><<<dim3(RB, 2), 256>>>(nullptr, 9, Wf2, bf2, nullptr, 10, -1, NN, 256, 128);
    k_gemm<64, 64, 32, 4, 4, 2><<<dim3(RB, 1), 256>>>(nullptr, 10, Wf3, bf3, nullptr, 11, -1, NN, 128, 64);
    k_gemm<64, 32, 32, 4, 2, 3><<<dim3(RB, 1), 256>>>(nullptr, 11, Wf4, bf4, out, -1, -1, NN, 64, 10);
}